// round 15
// baseline (speedup 1.0000x reference)
#include <cuda_runtime.h>
#include <cuda_fp16.h>
#include <math.h>
#include <stdint.h>

// Problem constants (fixed-shape problem)
#define Nn   20000
#define Ee   100000
#define Ll   4
#define Dd   64
#define Hh   8
#define HIDc 512

// Weight-stationary persistent LSTM tiling:
// CTA = 1024 threads (32 warps = 8 M-warps x 4 N-warps), 1 CTA/SM.
// Warp tile 32 rows x 32 gate cols (8 hidden x 4 gates): B fragments reused
// across both m16 blocks -> 4 ldsm4 per 8 MMAs (was 5).
#define BMP  256        // edges per block-pass
#define BK   32         // K per chunk (32 fp16)
#define LDSW 20         // A ring row stride in words (80B, ldmatrix conflict-free)
#define A_STAGE_WORDS (BMP * LDSW)      // 5120
#define NSTAGE 3
#define B_WORDS (128 * 292)             // 128 rows x 1168B stride
#define DYN_SMEM ((B_WORDS + NSTAGE * A_STAGE_WORDS) * 4)   // 210944 B
#define NBLK ((Ee + BMP - 1) / BMP)     // 391 edge blocks
#define GRIDX 37                         // 37*16 = 592 CTAs = 4 waves of 148

// ---------------- scratch (device globals; no allocation allowed) ----------
__device__ float  g_h1[(size_t)Ee * HIDc];     // final-step h (fp32, attn/scatter)
__device__ float  g_c [(size_t)Ee * HIDc];     // cell state (fp32)
__device__ __half g_h16a[(size_t)Ee * HIDc];   // h ping (fp16, MMA operand)
__device__ __half g_h16b[(size_t)Ee * HIDc];   // h pong
__device__ float  g_a [(size_t)Ee * Hh];
__device__ float  g_amax[(size_t)Nn * Hh];
__device__ float  g_den [(size_t)Nn * Hh];
// fp16 operand copies
__device__ __half g_Wih_h [4 * HIDc * Dd];          // 2048 x 64
__device__ __half g_Whh_h [(size_t)4 * HIDc * HIDc];// 2048 x 512
__device__ __half g_feat_h[(size_t)Nn * Dd];        // 20000 x 64

// ---------------- helpers ----------------------------------------------------
__device__ __forceinline__ uint32_t smem_u32(const void* p) {
    uint32_t a;
    asm("{ .reg .u64 t; cvta.to.shared.u64 t, %1; cvt.u32.u64 %0, t; }"
        : "=r"(a) : "l"(p));
    return a;
}
static __device__ __forceinline__ void cpa16(uint32_t dst, const void* src) {
    asm volatile("cp.async.cg.shared.global [%0], [%1], 16;" :: "r"(dst), "l"(src));
}
#define CP_COMMIT() asm volatile("cp.async.commit_group;")
#define CP_WAIT1()  asm volatile("cp.async.wait_group 1;")
#define CP_WAIT0()  asm volatile("cp.async.wait_group 0;")

// warp-collective 4-fragment load (non-transposed)
__device__ __forceinline__ void ldsm4(uint32_t& r0, uint32_t& r1,
                                      uint32_t& r2, uint32_t& r3, uint32_t addr) {
    asm volatile("ldmatrix.sync.aligned.m8n8.x4.shared.b16 {%0,%1,%2,%3}, [%4];"
                 : "=r"(r0), "=r"(r1), "=r"(r2), "=r"(r3) : "r"(addr));
}

// m16n8k16 fp16 inputs, fp32 accumulate.
__device__ __forceinline__ void mma16(float* d, const uint32_t* a,
                                      uint32_t b0, uint32_t b1) {
    asm volatile(
        "mma.sync.aligned.m16n8k16.row.col.f32.f16.f16.f32 "
        "{%0,%1,%2,%3}, {%4,%5,%6,%7}, {%8,%9}, {%0,%1,%2,%3};"
        : "+f"(d[0]), "+f"(d[1]), "+f"(d[2]), "+f"(d[3])
        : "r"(a[0]), "r"(a[1]), "r"(a[2]), "r"(a[3]), "r"(b0), "r"(b1));
}

// ---------------- prep: fp16-round weights + features once -------------------
__global__ void prep_kernel(const float* __restrict__ Wih,
                            const float* __restrict__ Whh,
                            const float* __restrict__ feat) {
    int i = blockIdx.x * blockDim.x + threadIdx.x;
    if (i < 4 * HIDc * Dd)   g_Wih_h[i]  = __float2half_rn(Wih[i]);
    if (i < 4 * HIDc * HIDc) g_Whh_h[i]  = __float2half_rn(Whh[i]);
    if (i < Nn * Dd)         g_feat_h[i] = __float2half_rn(feat[i]);
}

// ---------------- init -------------------------------------------------------
__global__ void init_kernel(float* __restrict__ out) {
    int i = blockIdx.x * blockDim.x + threadIdx.x;
    if (i < Nn * HIDc) out[i] = 0.f;
    if (i < Nn * Hh) {
        g_amax[i] = __int_as_float(0xFF800000);
        g_den[i]  = 0.f;
    }
}

// ---------------- weight-stationary persistent LSTM step ---------------------
// gates(E x 2048) = x_t @ W_ih^T + h_prev @ W_hh^T (+bias in epilogue).
// B smem layout: row c (gate col, 0..127; weight row = (c>>5)*512 + nh0 + (c&31)),
// halves 0..63 = Wih k, halves 64..575 = Whh k; row stride 584 halves (1168B).
__global__ __launch_bounds__(1024, 1)
void lstm_mma_kernel(const int*   __restrict__ idx,
                     const float* __restrict__ bih,
                     const float* __restrict__ bhh,
                     int t)
{
    extern __shared__ uint32_t smem[];
    __shared__ int   rows_s[BMP];
    __shared__ float bias_s[128];

    const int tid   = threadIdx.x;
    const int wid   = tid >> 5;
    const int lane  = tid & 31;
    const int warpM = wid & 7;        // 0..7  (32 rows each)
    const int warpN = wid >> 3;       // 0..3  (8 hidden x 4 gates each)
    const int nh0   = blockIdx.y * 32;

    const __half* hprev16 = (t & 1) ? g_h16a : g_h16b;
    __half*       hnext16 = (t & 1) ? g_h16b : g_h16a;
    const bool first = (t == 0);
    const bool last  = (t == Ll - 1);
    const int  NC    = first ? 2 : 18;        // K chunks: 64 feat (+512 hidden)

    const uint32_t b_base = smem_u32(smem);
    const uint32_t a_base = b_base + (uint32_t)B_WORDS * 4u;

    // ---- load B (weights slice) into smem ONCE: 128 rows x 72 16B-chunks ----
    for (int j = tid; j < 128 * 72; j += 1024) {
        int row = j / 72, c = j % 72;
        int wrow = (row >> 5) * HIDc + nh0 + (row & 31);
        uint32_t dst = b_base + (uint32_t)row * 1168u
                     + (uint32_t)(c < 8 ? c * 16 : 128 + (c - 8) * 16);
        const __half* src = (c < 8)
            ? g_Wih_h + (size_t)wrow * Dd   + c * 8
            : g_Whh_h + (size_t)wrow * HIDc + (c - 8) * 8;
        cpa16(dst, src);
    }
    CP_COMMIT();
    if (tid < 128) {   // bias, c = g*32 + hh
        int g = tid >> 5, hh = tid & 31;
        int r = g * HIDc + nh0 + hh;
        bias_s[tid] = bih[r] + bhh[r];
    }
    CP_WAIT0();
    __syncthreads();

    // edge-block range for this CTA (balanced partition of 391 blocks over 37)
    const int eb0 = (blockIdx.x * NBLK) / GRIDX;
    const int eb1 = ((blockIdx.x + 1) * NBLK) / GRIDX;

    // A fill mapping: 1024 threads -> row rA (0..255), k-quarter kq (0..3)
    const int rA = tid >> 2;
    const int kq = tid & 3;

    // ldmatrix lane offsets (bytes), invariant:
    // A x4 (m16k16): lanes 0-15 rows +0..15 at kword; 16-31 same rows k+8.
    const uint32_t a_lane_off =
        ((uint32_t)((warpM * 32 + (lane & 15)) * LDSW + ((lane >> 4) << 2))) * 4u;
    // B x4 (gate pair p: gates 2p,2p+1), 8 hidden per warp:
    // lanes 0-7 g=2p k0-7; 8-15 g=2p k8-15; 16-23 g=2p+1 k0-7; 24-31 k8-15.
    const uint32_t b_lane_base = b_base
        + (uint32_t)((lane >> 4) * 32 + warpN * 8 + (lane & 7)) * 1168u
        + (uint32_t)(((lane >> 3) & 1) << 4);

    for (int eb = eb0; eb < eb1; eb++) {
        const int e0 = eb * BMP;
        if (tid < BMP) {
            int e = e0 + tid; if (e >= Ee) e = Ee - 1;
            rows_s[tid] = idx[e * Ll + t];
        }
        __syncthreads();   // rows_s ready; prior block's ring reads done

        int eA = e0 + rA; if (eA >= Ee) eA = Ee - 1;

        auto fillA = [&](int kc) {
            const int s = kc % NSTAGE;
            uint32_t dst = a_base
                + (uint32_t)(s * A_STAGE_WORDS + rA * LDSW + kq * 4) * 4u;
            const __half* ap = (kc < 2)
                ? g_feat_h + (size_t)rows_s[rA] * Dd + kc * BK + kq * 8
                : hprev16  + (size_t)eA * HIDc + (kc - 2) * BK + kq * 8;
            cpa16(dst, ap);
        };

        float acc[2][4][4];       // [mb][gate][frag]
#pragma unroll
        for (int mb = 0; mb < 2; mb++)
#pragma unroll
            for (int g = 0; g < 4; g++)
#pragma unroll
                for (int v = 0; v < 4; v++) acc[mb][g][v] = 0.f;

        fillA(0); CP_COMMIT();
        fillA(1); CP_COMMIT();

        for (int kc = 0; kc < NC; kc++) {
            CP_WAIT1();               // stage kc resident
            __syncthreads();          // publish stage kc
            if (kc + 2 < NC) fillA(kc + 2);
            CP_COMMIT();

            const int s = kc % NSTAGE;
            const uint32_t a_stage = a_base + (uint32_t)(s * A_STAGE_WORDS) * 4u;
            const uint32_t kbyte = (uint32_t)(kc < 2 ? kc * 64 : 128 + (kc - 2) * 64);
#pragma unroll
            for (int kk = 0; kk < 2; kk++) {      // 2 x k16 per 32-chunk
                const uint32_t koff = (uint32_t)(kk * 32);
                uint32_t afr[2][4];
                ldsm4(afr[0][0], afr[0][1], afr[0][2], afr[0][3],
                      a_stage + koff + a_lane_off);
                ldsm4(afr[1][0], afr[1][1], afr[1][2], afr[1][3],
                      a_stage + koff + a_lane_off + (uint32_t)(16 * LDSW) * 4u);
#pragma unroll
                for (int p = 0; p < 2; p++) {  // gate pairs (0,1),(2,3)
                    uint32_t q0, q1, q2, q3;
                    ldsm4(q0, q1, q2, q3,
                          b_lane_base + (uint32_t)(p * 64) * 1168u + kbyte + koff);
                    mma16(acc[0][2 * p],     afr[0], q0, q1);
                    mma16(acc[1][2 * p],     afr[1], q0, q1);
                    mma16(acc[0][2 * p + 1], afr[0], q2, q3);
                    mma16(acc[1][2 * p + 1], afr[1], q2, q3);
                }
            }
        }
        __syncthreads();   // all ring reads done before next block's fills

        // ---- epilogue: LSTM cell from accumulators --------------------------
#pragma unroll
        for (int mb = 0; mb < 2; mb++) {
#pragma unroll
            for (int rh = 0; rh < 2; rh++) {
                int e = e0 + warpM * 32 + mb * 16 + (lane >> 2) + rh * 8;
                if (e >= Ee) continue;
                float*  cp   = g_c     + (size_t)e * HIDc + nh0;
                __half* hp16 = hnext16 + (size_t)e * HIDc + nh0;
                float*  hp32 = g_h1    + (size_t)e * HIDc + nh0;
                int hh = warpN * 8 + (lane & 3) * 2;
                float2 cold = make_float2(0.f, 0.f);
                if (!first) cold = *(const float2*)(cp + hh);
                float cv[2], hv[2];
#pragma unroll
                for (int v = 0; v < 2; v++) {
                    int ci = rh * 2 + v;
                    float gi = acc[mb][0][ci] + bias_s[      hh + v];
                    float gf = acc[mb][1][ci] + bias_s[ 32 + hh + v];
                    float gg = acc[mb][2][ci] + bias_s[ 64 + hh + v];
                    float go = acc[mb][3][ci] + bias_s[ 96 + hh + v];
                    float si = 1.f / (1.f + __expf(-gi));
                    float sf = 1.f / (1.f + __expf(-gf));
                    float tg = tanhf(gg);
                    float so = 1.f / (1.f + __expf(-go));
                    float co = v ? cold.y : cold.x;
                    float cn = sf * co + si * tg;
                    cv[v] = cn;
                    hv[v] = so * tanhf(cn);
                }
                *(float2*)(cp + hh) = make_float2(cv[0], cv[1]);
                *(__half2*)(hp16 + hh) = __floats2half2_rn(hv[0], hv[1]);
                if (last) *(float2*)(hp32 + hh) = make_float2(hv[0], hv[1]);
            }
        }
    }
}

// ---------------- attention logits + segment max (warp per edge) -----------
__global__ void attn_logits_kernel(const float* __restrict__ feat,
                                   const int*   __restrict__ idx,
                                   const int*   __restrict__ dst,
                                   const float* __restrict__ attn1w,
                                   const float* __restrict__ attn2)
{
    int warp = (blockIdx.x * blockDim.x + threadIdx.x) >> 5;
    int lane = threadIdx.x & 31;
    if (warp >= Ee) return;
    const float* hlast = g_h1;

    int h   = lane >> 2;
    int seg = lane & 3;

    const float* eft = hlast + (size_t)warp * HIDc + h * Dd;
    const float* w2  = attn2  + h * Dd;
    int cidx = idx[warp * Ll + (Ll - 1)];
    const float* ctr = feat + (size_t)cidx * Dd;
    const float* w1  = attn1w + h * Dd;

    float s = 0.f;
#pragma unroll
    for (int q = 0; q < 4; q++) {
        int o = seg * 16 + q * 4;
        float4 ev = *(const float4*)(eft + o);
        float4 wv = *(const float4*)(w2 + o);
        float4 cv = *(const float4*)(ctr + o);
        float4 av = *(const float4*)(w1 + o);
        s += ev.x * wv.x + ev.y * wv.y + ev.z * wv.z + ev.w * wv.w;
        s += cv.x * av.x + cv.y * av.y + cv.z * av.z + cv.w * av.w;
    }
    s += __shfl_down_sync(0xffffffffu, s, 2);
    s += __shfl_down_sync(0xffffffffu, s, 1);

    if (seg == 0) {
        float a = (s > 0.f) ? s : 0.01f * s;
        g_a[(size_t)warp * Hh + h] = a;
        float* addr = &g_amax[(size_t)dst[warp] * Hh + h];
        if (a >= 0.f) atomicMax((int*)addr, __float_as_int(a));
        else          atomicMin((unsigned int*)addr, __float_as_uint(a));
    }
}

// ---------------- exp + denominator -----------------------------------------
__global__ void softmax_norm_kernel(const int* __restrict__ dst) {
    int i = blockIdx.x * blockDim.x + threadIdx.x;
    if (i >= Ee * Hh) return;
    int e = i >> 3, h = i & 7;
    int d = dst[e];
    float ex = __expf(g_a[i] - g_amax[(size_t)d * Hh + h]);
    g_a[i] = ex;
    atomicAdd(&g_den[(size_t)d * Hh + h], ex);
}

// ---------------- weighted segment scatter ----------------------------------
__global__ void scatter_out_kernel(const int* __restrict__ dst,
                                   float* __restrict__ out) {
    int i = blockIdx.x * blockDim.x + threadIdx.x;
    if (i >= Ee * HIDc) return;
    int e = i >> 9, col = i & 511, h = col >> 6;
    int d = dst[e];
    float w = g_a[(size_t)e * Hh + h] / g_den[(size_t)d * Hh + h];
    atomicAdd(out + (size_t)d * HIDc + col, g_h1[i] * w);
}

// ---------------- launch ------------------------------------------------------
extern "C" void kernel_launch(void* const* d_in, const int* in_sizes, int n_in,
                              void* d_out, int out_size)
{
    const float* feat = (const float*)d_in[0];
    const int*   idx  = (const int*)d_in[2];
    const int*   dst  = (const int*)d_in[3];
    const float* Wih  = (const float*)d_in[4];
    const float* Whh  = (const float*)d_in[5];
    const float* bih  = (const float*)d_in[6];
    const float* bhh  = (const float*)d_in[7];
    const float* a1w  = (const float*)d_in[8];
    const float* a2w  = (const float*)d_in[9];
    float* out = (float*)d_out;

    cudaFuncSetAttribute(lstm_mma_kernel,
                         cudaFuncAttributeMaxDynamicSharedMemorySize, DYN_SMEM);

    prep_kernel<<<(Nn * Dd + 255) / 256, 256>>>(Wih, Whh, feat);
    init_kernel<<<(Nn * HIDc + 255) / 256, 256>>>(out);

    dim3 lgrid(GRIDX, HIDc / 32);   // 37 x 16 = 592 CTAs = 4 full waves
    for (int t = 0; t < Ll; t++)
        lstm_mma_kernel<<<lgrid, 1024, DYN_SMEM>>>(idx, bih, bhh, t);

    attn_logits_kernel<<<(Ee * 32 + 255) / 256, 256>>>(feat, idx, dst, a1w, a2w);
    softmax_norm_kernel<<<(Ee * Hh + 255) / 256, 256>>>(dst);
    scatter_out_kernel<<<(Ee * HIDc + 255) / 256, 256>>>(dst, out);
}

// round 16
// speedup vs baseline: 1.0007x; 1.0007x over previous
#include <cuda_runtime.h>
#include <cuda_fp16.h>
#include <math.h>
#include <stdint.h>

// Problem constants (fixed-shape problem)
#define Nn   20000
#define Ee   100000
#define Ll   4
#define Dd   64
#define Hh   8
#define HIDc 512

// Weight-stationary persistent LSTM tiling:
// CTA = 1024 threads (32 warps = 8 M-warps x 4 N-warps), 1 CTA/SM.
// Warp tile 32 rows x 32 gate cols (8 hidden x 4 gates): B fragments reused
// across both m16 blocks -> 4 ldsm4 per 8 MMAs (was 5).
#define BMP  256        // edges per block-pass
#define BK   32         // K per chunk (32 fp16)
#define LDSW 20         // A ring row stride in words (80B, ldmatrix conflict-free)
#define A_STAGE_WORDS (BMP * LDSW)      // 5120
#define NSTAGE 3
#define B_WORDS (128 * 292)             // 128 rows x 1168B stride
#define DYN_SMEM ((B_WORDS + NSTAGE * A_STAGE_WORDS) * 4)   // 210944 B
#define NBLK ((Ee + BMP - 1) / BMP)     // 391 edge blocks
#define GRIDX 37                         // 37*16 = 592 CTAs = 4 waves of 148

// ---------------- scratch (device globals; no allocation allowed) ----------
__device__ float  g_h1[(size_t)Ee * HIDc];     // final-step h (fp32, attn/scatter)
__device__ float  g_c [(size_t)Ee * HIDc];     // cell state (fp32)
__device__ __half g_h16a[(size_t)Ee * HIDc];   // h ping (fp16, MMA operand)
__device__ __half g_h16b[(size_t)Ee * HIDc];   // h pong
__device__ float  g_a [(size_t)Ee * Hh];
__device__ float  g_amax[(size_t)Nn * Hh];
__device__ float  g_den [(size_t)Nn * Hh];
// fp16 operand copies
__device__ __half g_Wih_h [4 * HIDc * Dd];          // 2048 x 64
__device__ __half g_Whh_h [(size_t)4 * HIDc * HIDc];// 2048 x 512
__device__ __half g_feat_h[(size_t)Nn * Dd];        // 20000 x 64

// ---------------- helpers ----------------------------------------------------
__device__ __forceinline__ uint32_t smem_u32(const void* p) {
    uint32_t a;
    asm("{ .reg .u64 t; cvta.to.shared.u64 t, %1; cvt.u32.u64 %0, t; }"
        : "=r"(a) : "l"(p));
    return a;
}
static __device__ __forceinline__ void cpa16(uint32_t dst, const void* src) {
    asm volatile("cp.async.cg.shared.global [%0], [%1], 16;" :: "r"(dst), "l"(src));
}
#define CP_COMMIT() asm volatile("cp.async.commit_group;")
#define CP_WAIT1()  asm volatile("cp.async.wait_group 1;")
#define CP_WAIT0()  asm volatile("cp.async.wait_group 0;")

// warp-collective 4-fragment load (non-transposed)
__device__ __forceinline__ void ldsm4(uint32_t& r0, uint32_t& r1,
                                      uint32_t& r2, uint32_t& r3, uint32_t addr) {
    asm volatile("ldmatrix.sync.aligned.m8n8.x4.shared.b16 {%0,%1,%2,%3}, [%4];"
                 : "=r"(r0), "=r"(r1), "=r"(r2), "=r"(r3) : "r"(addr));
}

// m16n8k16 fp16 inputs, fp32 accumulate.
__device__ __forceinline__ void mma16(float* d, const uint32_t* a,
                                      uint32_t b0, uint32_t b1) {
    asm volatile(
        "mma.sync.aligned.m16n8k16.row.col.f32.f16.f16.f32 "
        "{%0,%1,%2,%3}, {%4,%5,%6,%7}, {%8,%9}, {%0,%1,%2,%3};"
        : "+f"(d[0]), "+f"(d[1]), "+f"(d[2]), "+f"(d[3])
        : "r"(a[0]), "r"(a[1]), "r"(a[2]), "r"(a[3]), "r"(b0), "r"(b1));
}

// ---------------- prep: fp16-round weights + features once -------------------
__global__ void prep_kernel(const float* __restrict__ Wih,
                            const float* __restrict__ Whh,
                            const float* __restrict__ feat) {
    int i = blockIdx.x * blockDim.x + threadIdx.x;
    if (i < 4 * HIDc * Dd)   g_Wih_h[i]  = __float2half_rn(Wih[i]);
    if (i < 4 * HIDc * HIDc) g_Whh_h[i]  = __float2half_rn(Whh[i]);
    if (i < Nn * Dd)         g_feat_h[i] = __float2half_rn(feat[i]);
}

// ---------------- init -------------------------------------------------------
__global__ void init_kernel(float* __restrict__ out) {
    int i = blockIdx.x * blockDim.x + threadIdx.x;
    if (i < Nn * HIDc) out[i] = 0.f;
    if (i < Nn * Hh) {
        g_amax[i] = __int_as_float(0xFF800000);
        g_den[i]  = 0.f;
    }
}

// ---------------- weight-stationary persistent LSTM step ---------------------
// gates(E x 2048) = x_t @ W_ih^T + h_prev @ W_hh^T (+bias in epilogue).
// B smem layout: row c (gate col, 0..127; weight row = (c>>5)*512 + nh0 + (c&31)),
// halves 0..63 = Wih k, halves 64..575 = Whh k; row stride 584 halves (1168B).
__global__ __launch_bounds__(1024, 1)
void lstm_mma_kernel(const int*   __restrict__ idx,
                     const float* __restrict__ bih,
                     const float* __restrict__ bhh,
                     int t)
{
    extern __shared__ uint32_t smem[];
    __shared__ int   rows_s[BMP];
    __shared__ float bias_s[128];

    const int tid   = threadIdx.x;
    const int wid   = tid >> 5;
    const int lane  = tid & 31;
    const int warpM = wid & 7;        // 0..7  (32 rows each)
    const int warpN = wid >> 3;       // 0..3  (8 hidden x 4 gates each)
    const int nh0   = blockIdx.y * 32;

    const __half* hprev16 = (t & 1) ? g_h16a : g_h16b;
    __half*       hnext16 = (t & 1) ? g_h16b : g_h16a;
    const bool first = (t == 0);
    const bool last  = (t == Ll - 1);
    const int  NC    = first ? 2 : 18;        // K chunks: 64 feat (+512 hidden)

    const uint32_t b_base = smem_u32(smem);
    const uint32_t a_base = b_base + (uint32_t)B_WORDS * 4u;

    // ---- load B (weights slice) into smem ONCE: 128 rows x 72 16B-chunks ----
    for (int j = tid; j < 128 * 72; j += 1024) {
        int row = j / 72, c = j % 72;
        int wrow = (row >> 5) * HIDc + nh0 + (row & 31);
        uint32_t dst = b_base + (uint32_t)row * 1168u
                     + (uint32_t)(c < 8 ? c * 16 : 128 + (c - 8) * 16);
        const __half* src = (c < 8)
            ? g_Wih_h + (size_t)wrow * Dd   + c * 8
            : g_Whh_h + (size_t)wrow * HIDc + (c - 8) * 8;
        cpa16(dst, src);
    }
    CP_COMMIT();
    if (tid < 128) {   // bias, c = g*32 + hh
        int g = tid >> 5, hh = tid & 31;
        int r = g * HIDc + nh0 + hh;
        bias_s[tid] = bih[r] + bhh[r];
    }
    CP_WAIT0();
    __syncthreads();

    // edge-block range for this CTA (balanced partition of 391 blocks over 37)
    const int eb0 = (blockIdx.x * NBLK) / GRIDX;
    const int eb1 = ((blockIdx.x + 1) * NBLK) / GRIDX;

    // A fill mapping: 1024 threads -> row rA (0..255), k-quarter kq (0..3)
    const int rA = tid >> 2;
    const int kq = tid & 3;

    // ldmatrix lane offsets (bytes), invariant:
    // A x4 (m16k16): lanes 0-15 rows +0..15 at kword; 16-31 same rows k+8.
    const uint32_t a_lane_off =
        ((uint32_t)((warpM * 32 + (lane & 15)) * LDSW + ((lane >> 4) << 2))) * 4u;
    // B x4 (gate pair p: gates 2p,2p+1), 8 hidden per warp:
    // lanes 0-7 g=2p k0-7; 8-15 g=2p k8-15; 16-23 g=2p+1 k0-7; 24-31 k8-15.
    const uint32_t b_lane_base = b_base
        + (uint32_t)((lane >> 4) * 32 + warpN * 8 + (lane & 7)) * 1168u
        + (uint32_t)(((lane >> 3) & 1) << 4);

    for (int eb = eb0; eb < eb1; eb++) {
        const int e0 = eb * BMP;
        if (tid < BMP) {
            int e = e0 + tid; if (e >= Ee) e = Ee - 1;
            rows_s[tid] = idx[e * Ll + t];
        }
        __syncthreads();   // rows_s ready; prior block's ring reads done

        int eA = e0 + rA; if (eA >= Ee) eA = Ee - 1;

        auto fillA = [&](int kc) {
            const int s = kc % NSTAGE;
            uint32_t dst = a_base
                + (uint32_t)(s * A_STAGE_WORDS + rA * LDSW + kq * 4) * 4u;
            const __half* ap = (kc < 2)
                ? g_feat_h + (size_t)rows_s[rA] * Dd + kc * BK + kq * 8
                : hprev16  + (size_t)eA * HIDc + (kc - 2) * BK + kq * 8;
            cpa16(dst, ap);
        };

        float acc[2][4][4];       // [mb][gate][frag]
#pragma unroll
        for (int mb = 0; mb < 2; mb++)
#pragma unroll
            for (int g = 0; g < 4; g++)
#pragma unroll
                for (int v = 0; v < 4; v++) acc[mb][g][v] = 0.f;

        fillA(0); CP_COMMIT();
        fillA(1); CP_COMMIT();

        for (int kc = 0; kc < NC; kc++) {
            CP_WAIT1();               // stage kc resident
            __syncthreads();          // publish stage kc
            if (kc + 2 < NC) fillA(kc + 2);
            CP_COMMIT();

            const int s = kc % NSTAGE;
            const uint32_t a_stage = a_base + (uint32_t)(s * A_STAGE_WORDS) * 4u;
            const uint32_t kbyte = (uint32_t)(kc < 2 ? kc * 64 : 128 + (kc - 2) * 64);
#pragma unroll
            for (int kk = 0; kk < 2; kk++) {      // 2 x k16 per 32-chunk
                const uint32_t koff = (uint32_t)(kk * 32);
                uint32_t afr[2][4];
                ldsm4(afr[0][0], afr[0][1], afr[0][2], afr[0][3],
                      a_stage + koff + a_lane_off);
                ldsm4(afr[1][0], afr[1][1], afr[1][2], afr[1][3],
                      a_stage + koff + a_lane_off + (uint32_t)(16 * LDSW) * 4u);
#pragma unroll
                for (int p = 0; p < 2; p++) {  // gate pairs (0,1),(2,3)
                    uint32_t q0, q1, q2, q3;
                    ldsm4(q0, q1, q2, q3,
                          b_lane_base + (uint32_t)(p * 64) * 1168u + kbyte + koff);
                    mma16(acc[0][2 * p],     afr[0], q0, q1);
                    mma16(acc[1][2 * p],     afr[1], q0, q1);
                    mma16(acc[0][2 * p + 1], afr[0], q2, q3);
                    mma16(acc[1][2 * p + 1], afr[1], q2, q3);
                }
            }
        }
        __syncthreads();   // all ring reads done before next block's fills

        // ---- epilogue: LSTM cell from accumulators --------------------------
#pragma unroll
        for (int mb = 0; mb < 2; mb++) {
#pragma unroll
            for (int rh = 0; rh < 2; rh++) {
                int e = e0 + warpM * 32 + mb * 16 + (lane >> 2) + rh * 8;
                if (e >= Ee) continue;
                float*  cp   = g_c     + (size_t)e * HIDc + nh0;
                __half* hp16 = hnext16 + (size_t)e * HIDc + nh0;
                float*  hp32 = g_h1    + (size_t)e * HIDc + nh0;
                int hh = warpN * 8 + (lane & 3) * 2;
                float2 cold = make_float2(0.f, 0.f);
                if (!first) cold = *(const float2*)(cp + hh);
                float cv[2], hv[2];
#pragma unroll
                for (int v = 0; v < 2; v++) {
                    int ci = rh * 2 + v;
                    float gi = acc[mb][0][ci] + bias_s[      hh + v];
                    float gf = acc[mb][1][ci] + bias_s[ 32 + hh + v];
                    float gg = acc[mb][2][ci] + bias_s[ 64 + hh + v];
                    float go = acc[mb][3][ci] + bias_s[ 96 + hh + v];
                    float si = 1.f / (1.f + __expf(-gi));
                    float sf = 1.f / (1.f + __expf(-gf));
                    float tg = tanhf(gg);
                    float so = 1.f / (1.f + __expf(-go));
                    float co = v ? cold.y : cold.x;
                    float cn = sf * co + si * tg;
                    cv[v] = cn;
                    hv[v] = so * tanhf(cn);
                }
                *(float2*)(cp + hh) = make_float2(cv[0], cv[1]);
                *(__half2*)(hp16 + hh) = __floats2half2_rn(hv[0], hv[1]);
                if (last) *(float2*)(hp32 + hh) = make_float2(hv[0], hv[1]);
            }
        }
    }
}

// ---------------- attention logits + segment max (warp per edge) -----------
__global__ void attn_logits_kernel(const float* __restrict__ feat,
                                   const int*   __restrict__ idx,
                                   const int*   __restrict__ dst,
                                   const float* __restrict__ attn1w,
                                   const float* __restrict__ attn2)
{
    int warp = (blockIdx.x * blockDim.x + threadIdx.x) >> 5;
    int lane = threadIdx.x & 31;
    if (warp >= Ee) return;
    const float* hlast = g_h1;

    int h   = lane >> 2;
    int seg = lane & 3;

    const float* eft = hlast + (size_t)warp * HIDc + h * Dd;
    const float* w2  = attn2  + h * Dd;
    int cidx = idx[warp * Ll + (Ll - 1)];
    const float* ctr = feat + (size_t)cidx * Dd;
    const float* w1  = attn1w + h * Dd;

    float s = 0.f;
#pragma unroll
    for (int q = 0; q < 4; q++) {
        int o = seg * 16 + q * 4;
        float4 ev = *(const float4*)(eft + o);
        float4 wv = *(const float4*)(w2 + o);
        float4 cv = *(const float4*)(ctr + o);
        float4 av = *(const float4*)(w1 + o);
        s += ev.x * wv.x + ev.y * wv.y + ev.z * wv.z + ev.w * wv.w;
        s += cv.x * av.x + cv.y * av.y + cv.z * av.z + cv.w * av.w;
    }
    s += __shfl_down_sync(0xffffffffu, s, 2);
    s += __shfl_down_sync(0xffffffffu, s, 1);

    if (seg == 0) {
        float a = (s > 0.f) ? s : 0.01f * s;
        g_a[(size_t)warp * Hh + h] = a;
        float* addr = &g_amax[(size_t)dst[warp] * Hh + h];
        if (a >= 0.f) atomicMax((int*)addr, __float_as_int(a));
        else          atomicMin((unsigned int*)addr, __float_as_uint(a));
    }
}

// ---------------- exp + denominator -----------------------------------------
__global__ void softmax_norm_kernel(const int* __restrict__ dst) {
    int i = blockIdx.x * blockDim.x + threadIdx.x;
    if (i >= Ee * Hh) return;
    int e = i >> 3, h = i & 7;
    int d = dst[e];
    float ex = __expf(g_a[i] - g_amax[(size_t)d * Hh + h]);
    g_a[i] = ex;
    atomicAdd(&g_den[(size_t)d * Hh + h], ex);
}

// ---------------- weighted segment scatter ----------------------------------
__global__ void scatter_out_kernel(const int* __restrict__ dst,
                                   float* __restrict__ out) {
    int i = blockIdx.x * blockDim.x + threadIdx.x;
    if (i >= Ee * HIDc) return;
    int e = i >> 9, col = i & 511, h = col >> 6;
    int d = dst[e];
    float w = g_a[(size_t)e * Hh + h] / g_den[(size_t)d * Hh + h];
    atomicAdd(out + (size_t)d * HIDc + col, g_h1[i] * w);
}

// ---------------- launch ------------------------------------------------------
extern "C" void kernel_launch(void* const* d_in, const int* in_sizes, int n_in,
                              void* d_out, int out_size)
{
    const float* feat = (const float*)d_in[0];
    const int*   idx  = (const int*)d_in[2];
    const int*   dst  = (const int*)d_in[3];
    const float* Wih  = (const float*)d_in[4];
    const float* Whh  = (const float*)d_in[5];
    const float* bih  = (const float*)d_in[6];
    const float* bhh  = (const float*)d_in[7];
    const float* a1w  = (const float*)d_in[8];
    const float* a2w  = (const float*)d_in[9];
    float* out = (float*)d_out;

    cudaFuncSetAttribute(lstm_mma_kernel,
                         cudaFuncAttributeMaxDynamicSharedMemorySize, DYN_SMEM);

    prep_kernel<<<(Nn * Dd + 255) / 256, 256>>>(Wih, Whh, feat);
    init_kernel<<<(Nn * HIDc + 255) / 256, 256>>>(out);

    dim3 lgrid(GRIDX, HIDc / 32);   // 37 x 16 = 592 CTAs = 4 full waves
    for (int t = 0; t < Ll; t++)
        lstm_mma_kernel<<<lgrid, 1024, DYN_SMEM>>>(idx, bih, bhh, t);

    attn_logits_kernel<<<(Ee * 32 + 255) / 256, 256>>>(feat, idx, dst, a1w, a2w);
    softmax_norm_kernel<<<(Ee * Hh + 255) / 256, 256>>>(dst);
    scatter_out_kernel<<<(Ee * HIDc + 255) / 256, 256>>>(dst, out);
}

// round 17
// speedup vs baseline: 1.1927x; 1.1918x over previous
#include <cuda_runtime.h>
#include <cuda_fp16.h>
#include <math.h>
#include <stdint.h>

// Problem constants (fixed-shape problem)
#define Nn   20000
#define Ee   100000
#define Ll   4
#define Dd   64
#define Hh   8
#define HIDc 512

// Weight-stationary persistent LSTM tiling:
// CTA = 1024 threads (32 warps = 8 M-warps x 4 N-warps), 1 CTA/SM.
// Warp tile 32 rows x 32 gate cols. BK=64 chunks, 2-stage A ring:
// 9 barrier rounds per block-pass (was 18), 32-MMA trains per round.
#define BMP  256        // edges per block-pass
#define BK   64         // K per chunk (64 fp16 = 128B per row)
#define LDSW 36         // A ring row stride in words (144B: ldmatrix conflict-free)
#define A_STAGE_WORDS (BMP * LDSW)      // 9216 words = 36864 B
#define NSTAGE 2
#define B_WORDS (128 * 292)             // 128 rows x 1168B stride = 149504 B
#define DYN_SMEM ((B_WORDS + NSTAGE * A_STAGE_WORDS) * 4)   // 223232 B
#define NBLK ((Ee + BMP - 1) / BMP)     // 391 edge blocks
#define GRIDX 37                         // 37*16 = 592 CTAs = 4 waves of 148

// ---------------- scratch (device globals; no allocation allowed) ----------
__device__ float  g_h1[(size_t)Ee * HIDc];     // final-step h (fp32, attn/scatter)
__device__ float  g_c [(size_t)Ee * HIDc];     // cell state (fp32)
__device__ __half g_h16a[(size_t)Ee * HIDc];   // h ping (fp16, MMA operand)
__device__ __half g_h16b[(size_t)Ee * HIDc];   // h pong
__device__ float  g_a [(size_t)Ee * Hh];
__device__ float  g_amax[(size_t)Nn * Hh];
__device__ float  g_den [(size_t)Nn * Hh];
// fp16 operand copies
__device__ __half g_Wih_h [4 * HIDc * Dd];          // 2048 x 64
__device__ __half g_Whh_h [(size_t)4 * HIDc * HIDc];// 2048 x 512
__device__ __half g_feat_h[(size_t)Nn * Dd];        // 20000 x 64

// ---------------- helpers ----------------------------------------------------
__device__ __forceinline__ uint32_t smem_u32(const void* p) {
    uint32_t a;
    asm("{ .reg .u64 t; cvta.to.shared.u64 t, %1; cvt.u32.u64 %0, t; }"
        : "=r"(a) : "l"(p));
    return a;
}
static __device__ __forceinline__ void cpa16(uint32_t dst, const void* src) {
    asm volatile("cp.async.cg.shared.global [%0], [%1], 16;" :: "r"(dst), "l"(src));
}
#define CP_COMMIT() asm volatile("cp.async.commit_group;")
#define CP_WAIT0()  asm volatile("cp.async.wait_group 0;")

// warp-collective 4-fragment load (non-transposed)
__device__ __forceinline__ void ldsm4(uint32_t& r0, uint32_t& r1,
                                      uint32_t& r2, uint32_t& r3, uint32_t addr) {
    asm volatile("ldmatrix.sync.aligned.m8n8.x4.shared.b16 {%0,%1,%2,%3}, [%4];"
                 : "=r"(r0), "=r"(r1), "=r"(r2), "=r"(r3) : "r"(addr));
}

// m16n8k16 fp16 inputs, fp32 accumulate.
__device__ __forceinline__ void mma16(float* d, const uint32_t* a,
                                      uint32_t b0, uint32_t b1) {
    asm volatile(
        "mma.sync.aligned.m16n8k16.row.col.f32.f16.f16.f32 "
        "{%0,%1,%2,%3}, {%4,%5,%6,%7}, {%8,%9}, {%0,%1,%2,%3};"
        : "+f"(d[0]), "+f"(d[1]), "+f"(d[2]), "+f"(d[3])
        : "r"(a[0]), "r"(a[1]), "r"(a[2]), "r"(a[3]), "r"(b0), "r"(b1));
}

// fast transcendentals (MUFU ex2 + rcp; saturate correctly at +/-inf)
__device__ __forceinline__ float sigm_f(float x) {
    return __fdividef(1.f, 1.f + __expf(-x));
}
__device__ __forceinline__ float tanh_f(float x) {
    return 1.f - __fdividef(2.f, __expf(2.f * x) + 1.f);
}

// ---------------- prep: fp16-round weights + features once -------------------
__global__ void prep_kernel(const float* __restrict__ Wih,
                            const float* __restrict__ Whh,
                            const float* __restrict__ feat) {
    int i = blockIdx.x * blockDim.x + threadIdx.x;
    if (i < 4 * HIDc * Dd)   g_Wih_h[i]  = __float2half_rn(Wih[i]);
    if (i < 4 * HIDc * HIDc) g_Whh_h[i]  = __float2half_rn(Whh[i]);
    if (i < Nn * Dd)         g_feat_h[i] = __float2half_rn(feat[i]);
}

// ---------------- init -------------------------------------------------------
__global__ void init_kernel(float* __restrict__ out) {
    int i = blockIdx.x * blockDim.x + threadIdx.x;
    if (i < Nn * HIDc) out[i] = 0.f;
    if (i < Nn * Hh) {
        g_amax[i] = __int_as_float(0xFF800000);
        g_den[i]  = 0.f;
    }
}

// ---------------- weight-stationary persistent LSTM step ---------------------
// gates(E x 2048) = x_t @ W_ih^T + h_prev @ W_hh^T (+bias in epilogue).
// B smem layout: row c (gate col, 0..127; weight row = (c>>5)*512 + nh0 + (c&31)),
// bytes 0..127 = Wih k (64 halves), bytes 128..1151 = Whh k; stride 1168B.
__global__ __launch_bounds__(1024, 1)
void lstm_mma_kernel(const int*   __restrict__ idx,
                     const float* __restrict__ bih,
                     const float* __restrict__ bhh,
                     int t)
{
    extern __shared__ uint32_t smem[];
    __shared__ int   rows_s[BMP];
    __shared__ float bias_s[128];

    const int tid   = threadIdx.x;
    const int wid   = tid >> 5;
    const int lane  = tid & 31;
    const int warpM = wid & 7;        // 0..7  (32 rows each)
    const int warpN = wid >> 3;       // 0..3  (8 hidden x 4 gates each)
    const int nh0   = blockIdx.y * 32;

    const __half* hprev16 = (t & 1) ? g_h16a : g_h16b;
    __half*       hnext16 = (t & 1) ? g_h16b : g_h16a;
    const bool first = (t == 0);
    const bool last  = (t == Ll - 1);
    const int  NC    = first ? 1 : 9;         // 64-wide chunks: 1 feat (+8 hidden)

    const uint32_t b_base = smem_u32(smem);
    const uint32_t a_base = b_base + (uint32_t)B_WORDS * 4u;

    // ---- load B (weights slice) into smem ONCE: 128 rows x 72 16B-chunks ----
    for (int j = tid; j < 128 * 72; j += 1024) {
        int row = j / 72, c = j % 72;
        int wrow = (row >> 5) * HIDc + nh0 + (row & 31);
        uint32_t dst = b_base + (uint32_t)row * 1168u
                     + (uint32_t)(c < 8 ? c * 16 : 128 + (c - 8) * 16);
        const __half* src = (c < 8)
            ? g_Wih_h + (size_t)wrow * Dd   + c * 8
            : g_Whh_h + (size_t)wrow * HIDc + (c - 8) * 8;
        cpa16(dst, src);
    }
    CP_COMMIT();
    if (tid < 128) {   // bias, c = g*32 + hh
        int g = tid >> 5, hh = tid & 31;
        int r = g * HIDc + nh0 + hh;
        bias_s[tid] = bih[r] + bhh[r];
    }
    CP_WAIT0();
    __syncthreads();

    // edge-block range for this CTA (balanced partition of 391 blocks over 37)
    const int eb0 = (blockIdx.x * NBLK) / GRIDX;
    const int eb1 = ((blockIdx.x + 1) * NBLK) / GRIDX;

    // A fill mapping: 1024 threads -> row rA (0..255), k-quarter kq (0..3);
    // each thread copies 32B (2x cp.async.16) of the 128B row chunk.
    const int rA = tid >> 2;
    const int kq = tid & 3;

    // ldmatrix lane offsets (bytes), invariant:
    const uint32_t a_lane_off =
        ((uint32_t)((warpM * 32 + (lane & 15)) * LDSW + ((lane >> 4) << 2))) * 4u;
    const uint32_t b_lane_base = b_base
        + (uint32_t)((lane >> 4) * 32 + warpN * 8 + (lane & 7)) * 1168u
        + (uint32_t)(((lane >> 3) & 1) << 4);

    for (int eb = eb0; eb < eb1; eb++) {
        const int e0 = eb * BMP;
        if (tid < BMP) {
            int e = e0 + tid; if (e >= Ee) e = Ee - 1;
            rows_s[tid] = idx[e * Ll + t];
        }
        __syncthreads();   // rows_s ready; prior block's ring reads done

        int eA = e0 + rA; if (eA >= Ee) eA = Ee - 1;

        auto fillA = [&](int kc) {
            const int s = kc & 1;
            uint32_t dst = a_base
                + (uint32_t)(s * A_STAGE_WORDS + rA * LDSW + kq * 8) * 4u;
            const __half* ap = (kc < 1)
                ? g_feat_h + (size_t)rows_s[rA] * Dd + kq * 16
                : hprev16  + (size_t)eA * HIDc + (kc - 1) * BK + kq * 16;
            cpa16(dst,      ap);
            cpa16(dst + 16, ap + 8);
        };

        float acc[2][4][4];       // [mb][gate][frag]
#pragma unroll
        for (int mb = 0; mb < 2; mb++)
#pragma unroll
            for (int g = 0; g < 4; g++)
#pragma unroll
                for (int v = 0; v < 4; v++) acc[mb][g][v] = 0.f;

        fillA(0); CP_COMMIT();

        for (int kc = 0; kc < NC; kc++) {
            CP_WAIT0();               // chunk kc resident (sole pending group)
            __syncthreads();          // publish; orders prior compute/overwrite
            if (kc + 1 < NC) fillA(kc + 1);
            CP_COMMIT();

            const uint32_t a_stage = a_base
                + (uint32_t)((kc & 1) * A_STAGE_WORDS) * 4u;
            const uint32_t kbyte = (uint32_t)(kc < 1 ? 0 : 128 + (kc - 1) * 128);
#pragma unroll
            for (int kk = 0; kk < 4; kk++) {      // 4 x k16 per 64-chunk
                const uint32_t koff = (uint32_t)(kk * 32);
                uint32_t afr[2][4];
                ldsm4(afr[0][0], afr[0][1], afr[0][2], afr[0][3],
                      a_stage + koff + a_lane_off);
                ldsm4(afr[1][0], afr[1][1], afr[1][2], afr[1][3],
                      a_stage + koff + a_lane_off + (uint32_t)(16 * LDSW) * 4u);
#pragma unroll
                for (int p = 0; p < 2; p++) {  // gate pairs (0,1),(2,3)
                    uint32_t q0, q1, q2, q3;
                    ldsm4(q0, q1, q2, q3,
                          b_lane_base + (uint32_t)(p * 64) * 1168u + kbyte + koff);
                    mma16(acc[0][2 * p],     afr[0], q0, q1);
                    mma16(acc[1][2 * p],     afr[1], q0, q1);
                    mma16(acc[0][2 * p + 1], afr[0], q2, q3);
                    mma16(acc[1][2 * p + 1], afr[1], q2, q3);
                }
            }
        }
        __syncthreads();   // all ring reads done before next block's fills

        // ---- epilogue: LSTM cell from accumulators (fast transcendentals) ---
#pragma unroll
        for (int mb = 0; mb < 2; mb++) {
#pragma unroll
            for (int rh = 0; rh < 2; rh++) {
                int e = e0 + warpM * 32 + mb * 16 + (lane >> 2) + rh * 8;
                if (e >= Ee) continue;
                float*  cp   = g_c     + (size_t)e * HIDc + nh0;
                __half* hp16 = hnext16 + (size_t)e * HIDc + nh0;
                float*  hp32 = g_h1    + (size_t)e * HIDc + nh0;
                int hh = warpN * 8 + (lane & 3) * 2;
                float2 cold = make_float2(0.f, 0.f);
                if (!first) cold = *(const float2*)(cp + hh);
                float cv[2], hv[2];
#pragma unroll
                for (int v = 0; v < 2; v++) {
                    int ci = rh * 2 + v;
                    float gi = acc[mb][0][ci] + bias_s[      hh + v];
                    float gf = acc[mb][1][ci] + bias_s[ 32 + hh + v];
                    float gg = acc[mb][2][ci] + bias_s[ 64 + hh + v];
                    float go = acc[mb][3][ci] + bias_s[ 96 + hh + v];
                    float si = sigm_f(gi);
                    float sf = sigm_f(gf);
                    float tg = tanh_f(gg);
                    float so = sigm_f(go);
                    float co = v ? cold.y : cold.x;
                    float cn = sf * co + si * tg;
                    cv[v] = cn;
                    hv[v] = so * tanh_f(cn);
                }
                *(float2*)(cp + hh) = make_float2(cv[0], cv[1]);
                *(__half2*)(hp16 + hh) = __floats2half2_rn(hv[0], hv[1]);
                if (last) *(float2*)(hp32 + hh) = make_float2(hv[0], hv[1]);
            }
        }
    }
}

// ---------------- attention logits + segment max (warp per edge) -----------
__global__ void attn_logits_kernel(const float* __restrict__ feat,
                                   const int*   __restrict__ idx,
                                   const int*   __restrict__ dst,
                                   const float* __restrict__ attn1w,
                                   const float* __restrict__ attn2)
{
    int warp = (blockIdx.x * blockDim.x + threadIdx.x) >> 5;
    int lane = threadIdx.x & 31;
    if (warp >= Ee) return;
    const float* hlast = g_h1;

    int h   = lane >> 2;
    int seg = lane & 3;

    const float* eft = hlast + (size_t)warp * HIDc + h * Dd;
    const float* w2  = attn2  + h * Dd;
    int cidx = idx[warp * Ll + (Ll - 1)];
    const float* ctr = feat + (size_t)cidx * Dd;
    const float* w1  = attn1w + h * Dd;

    float s = 0.f;
#pragma unroll
    for (int q = 0; q < 4; q++) {
        int o = seg * 16 + q * 4;
        float4 ev = *(const float4*)(eft + o);
        float4 wv = *(const float4*)(w2 + o);
        float4 cv = *(const float4*)(ctr + o);
        float4 av = *(const float4*)(w1 + o);
        s += ev.x * wv.x + ev.y * wv.y + ev.z * wv.z + ev.w * wv.w;
        s += cv.x * av.x + cv.y * av.y + cv.z * av.z + cv.w * av.w;
    }
    s += __shfl_down_sync(0xffffffffu, s, 2);
    s += __shfl_down_sync(0xffffffffu, s, 1);

    if (seg == 0) {
        float a = (s > 0.f) ? s : 0.01f * s;
        g_a[(size_t)warp * Hh + h] = a;
        float* addr = &g_amax[(size_t)dst[warp] * Hh + h];
        if (a >= 0.f) atomicMax((int*)addr, __float_as_int(a));
        else          atomicMin((unsigned int*)addr, __float_as_uint(a));
    }
}

// ---------------- exp + denominator -----------------------------------------
__global__ void softmax_norm_kernel(const int* __restrict__ dst) {
    int i = blockIdx.x * blockDim.x + threadIdx.x;
    if (i >= Ee * Hh) return;
    int e = i >> 3, h = i & 7;
    int d = dst[e];
    float ex = __expf(g_a[i] - g_amax[(size_t)d * Hh + h]);
    g_a[i] = ex;
    atomicAdd(&g_den[(size_t)d * Hh + h], ex);
}

// ---------------- weighted segment scatter ----------------------------------
__global__ void scatter_out_kernel(const int* __restrict__ dst,
                                   float* __restrict__ out) {
    int i = blockIdx.x * blockDim.x + threadIdx.x;
    if (i >= Ee * HIDc) return;
    int e = i >> 9, col = i & 511, h = col >> 6;
    int d = dst[e];
    float w = g_a[(size_t)e * Hh + h] / g_den[(size_t)d * Hh + h];
    atomicAdd(out + (size_t)d * HIDc + col, g_h1[i] * w);
}

// ---------------- launch ------------------------------------------------------
extern "C" void kernel_launch(void* const* d_in, const int* in_sizes, int n_in,
                              void* d_out, int out_size)
{
    const float* feat = (const float*)d_in[0];
    const int*   idx  = (const int*)d_in[2];
    const int*   dst  = (const int*)d_in[3];
    const float* Wih  = (const float*)d_in[4];
    const float* Whh  = (const float*)d_in[5];
    const float* bih  = (const float*)d_in[6];
    const float* bhh  = (const float*)d_in[7];
    const float* a1w  = (const float*)d_in[8];
    const float* a2w  = (const float*)d_in[9];
    float* out = (float*)d_out;

    cudaFuncSetAttribute(lstm_mma_kernel,
                         cudaFuncAttributeMaxDynamicSharedMemorySize, DYN_SMEM);

    prep_kernel<<<(Nn * Dd + 255) / 256, 256>>>(Wih, Whh, feat);
    init_kernel<<<(Nn * HIDc + 255) / 256, 256>>>(out);

    dim3 lgrid(GRIDX, HIDc / 32);   // 37 x 16 = 592 CTAs = 4 full waves
    for (int t = 0; t < Ll; t++)
        lstm_mma_kernel<<<lgrid, 1024, DYN_SMEM>>>(idx, bih, bhh, t);

    attn_logits_kernel<<<(Ee * 32 + 255) / 256, 256>>>(feat, idx, dst, a1w, a2w);
    softmax_norm_kernel<<<(Ee * Hh + 255) / 256, 256>>>(dst);
    scatter_out_kernel<<<(Ee * HIDc + 255) / 256, 256>>>(dst, out);
}